// round 1
// baseline (speedup 1.0000x reference)
#include <cuda_runtime.h>
#include <math.h>

#define N_INST 8192
#define DIM    2048
#define NC     256
#define ALPHA  7.18f
#define MINM   4

// ---------------- scratch (no allocs allowed) ----------------
__device__ float g_means [NC * DIM];    // [C][D]  row-major (for resid pass)
__device__ float g_meansT[DIM * NC];    // [D][C]  (for coalesced GEMM B loads)
__device__ float g_mean_sq[NC];         // ||mu_c||^2
__device__ float g_counts [NC];
__device__ int   g_valid  [NC];
__device__ float g_xsq  [N_INST];       // ||x_i||^2
__device__ float g_rnorm[N_INST];       // ||x_i - mu_{cl(i)}||
__device__ float g_stats[3];            // [0]=stdev [1]=num_instances [2]=loss accum

// ---------------- K1: per-cluster means (block per cluster) ----------------
__global__ void __launch_bounds__(256) k_means(const float* __restrict__ X,
                                               const int* __restrict__ cl) {
    __shared__ int   sh_list[N_INST];
    __shared__ int   sh_cnt[256];
    __shared__ int   sh_off[256];
    __shared__ float red[256];

    const int c = blockIdx.x;
    const int t = threadIdx.x;
    const int CH = N_INST / 256;         // 32 indices per thread

    // deterministic compaction: count per chunk, serial prefix, ordered scatter
    int base = t * CH;
    int cnt = 0;
    #pragma unroll 8
    for (int j = 0; j < CH; j++) cnt += (cl[base + j] == c);
    sh_cnt[t] = cnt;
    __syncthreads();
    if (t == 0) {
        int s = 0;
        for (int i = 0; i < 256; i++) { sh_off[i] = s; s += sh_cnt[i]; }
    }
    __syncthreads();
    int off = sh_off[t];
    for (int j = 0; j < CH; j++) {
        int idx = base + j;
        if (cl[idx] == c) sh_list[off++] = idx;
    }
    __syncthreads();
    const int total = sh_off[255] + sh_cnt[255];

    // accumulate member rows; thread t owns columns t, t+256, ... (coalesced)
    float acc[8];
    #pragma unroll
    for (int j = 0; j < 8; j++) acc[j] = 0.0f;
    for (int m = 0; m < total; m++) {
        const float* row = X + (size_t)sh_list[m] * DIM;
        #pragma unroll
        for (int j = 0; j < 8; j++) acc[j] += row[t + j * 256];
    }

    const float inv = 1.0f / fmaxf((float)total, 1.0f);
    float msq = 0.0f;
    #pragma unroll
    for (int j = 0; j < 8; j++) {
        float mu = acc[j] * inv;
        int d = t + j * 256;
        g_means [(size_t)c * DIM + d] = mu;
        g_meansT[(size_t)d * NC  + c] = mu;
        msq += mu * mu;
    }
    red[t] = msq;
    __syncthreads();
    for (int s = 128; s > 0; s >>= 1) {
        if (t < s) red[t] += red[t + s];
        __syncthreads();
    }
    if (t == 0) {
        g_mean_sq[c] = red[0];
        g_counts[c]  = (float)total;
        g_valid[c]   = (total >= MINM) ? 1 : 0;
    }
}

// ---------------- K2: per-row ||x||^2 and residual norm ----------------
__global__ void __launch_bounds__(256) k_resid(const float* __restrict__ X,
                                               const int* __restrict__ cl) {
    __shared__ float r1[256], r2[256];
    const int i = blockIdx.x;
    const int t = threadIdx.x;
    const int c = cl[i];
    const float* row = X + (size_t)i * DIM;
    const float* mu  = g_means + (size_t)c * DIM;

    float sx = 0.0f, sr = 0.0f;
    #pragma unroll
    for (int j = 0; j < 8; j++) {
        float x = row[t + j * 256];
        float m = mu [t + j * 256];
        sx += x * x;
        float d = x - m;
        sr += d * d;
    }
    r1[t] = sx; r2[t] = sr;
    __syncthreads();
    for (int s = 128; s > 0; s >>= 1) {
        if (t < s) { r1[t] += r1[t + s]; r2[t] += r2[t + s]; }
        __syncthreads();
    }
    if (t == 0) {
        g_xsq  [i] = r1[0];
        g_rnorm[i] = sqrtf(r2[0]);
    }
}

// ---------------- K3: global stats (stdev quirk) + zero loss accum ----------------
__global__ void __launch_bounds__(256) k_stats(const int* __restrict__ cl) {
    __shared__ float red[256];
    __shared__ float s_ni;
    const int t = threadIdx.x;

    // num_instances = sum over valid clusters of counts  (one cluster per thread)
    red[t] = g_valid[t] ? g_counts[t] : 0.0f;
    __syncthreads();
    for (int s = 128; s > 0; s >>= 1) {
        if (t < s) red[t] += red[t + s];
        __syncthreads();
    }
    if (t == 0) s_ni = red[0];
    __syncthreads();

    // sum of resid norms over valid instances
    float sn = 0.0f;
    for (int i = t; i < N_INST; i += 256)
        sn += g_valid[cl[i]] ? g_rnorm[i] : 0.0f;
    red[t] = sn;
    __syncthreads();
    for (int s = 128; s > 0; s >>= 1) {
        if (t < s) red[t] += red[t + s];
        __syncthreads();
    }
    if (t == 0) {
        float s = red[0];
        g_stats[0] = (s * s) / s_ni;  // stdev quirk from reference
        g_stats[1] = s_ni;
        g_stats[2] = 0.0f;            // loss accumulator (re-zeroed each replay)
    }
}

// ---------------- K4: fused GEMM (dist) + epilogue (denom, loss) ----------------
// Block tile: 32 rows x 256 clusters, K tiled by 16. 256 threads = 8 warps.
// warp ty owns rows ty*4..ty*4+3; lane tx owns cols tx, tx+32, ..., tx+224.
__global__ void __launch_bounds__(256) k_gemm(const float* __restrict__ X,
                                              const int* __restrict__ cl) {
    __shared__ float As[32 * 16];    // [row][k]
    __shared__ float Bs[16 * 256];   // [k][c]

    const int t  = threadIdx.x;
    const int ty = t >> 5;
    const int tx = t & 31;
    const int row0 = blockIdx.x * 32;

    float acc[4][8];
    #pragma unroll
    for (int j = 0; j < 4; j++)
        #pragma unroll
        for (int m = 0; m < 8; m++) acc[j][m] = 0.0f;

    // A-load mapping: 512 floats = 256 float2; thread t -> row t/8, k = 2*(t%8)
    const int ar = t >> 3;
    const int ak = (t & 7) * 2;
    const float* arow = X + (size_t)(row0 + ar) * DIM + ak;

    for (int kk = 0; kk < DIM; kk += 16) {
        float2 av = *(const float2*)(arow + kk);
        As[ar * 16 + ak]     = av.x;
        As[ar * 16 + ak + 1] = av.y;
        #pragma unroll
        for (int j = 0; j < 16; j++)
            Bs[j * 256 + t] = g_meansT[(size_t)(kk + j) * NC + t];
        __syncthreads();

        #pragma unroll
        for (int k = 0; k < 16; k++) {
            float a0 = As[(ty * 4 + 0) * 16 + k];
            float a1 = As[(ty * 4 + 1) * 16 + k];
            float a2 = As[(ty * 4 + 2) * 16 + k];
            float a3 = As[(ty * 4 + 3) * 16 + k];
            float b[8];
            #pragma unroll
            for (int m = 0; m < 8; m++) b[m] = Bs[k * 256 + tx + m * 32];
            #pragma unroll
            for (int m = 0; m < 8; m++) {
                acc[0][m] = fmaf(a0, b[m], acc[0][m]);
                acc[1][m] = fmaf(a1, b[m], acc[1][m]);
                acc[2][m] = fmaf(a2, b[m], acc[2][m]);
                acc[3][m] = fmaf(a3, b[m], acc[3][m]);
            }
        }
        __syncthreads();
    }

    // ---- epilogue ----
    const float stdev = g_stats[0];
    const float sc = -0.5f / stdev;

    float msq[8]; int vld[8];
    #pragma unroll
    for (int m = 0; m < 8; m++) {
        int c = tx + m * 32;
        msq[m] = g_mean_sq[c];
        vld[m] = g_valid[c];
    }

    float lsum = 0.0f;
    #pragma unroll
    for (int j = 0; j < 4; j++) {
        int r  = row0 + ty * 4 + j;
        int cr = cl[r];
        float xs = g_xsq[r];
        float part = 0.0f;
        #pragma unroll
        for (int m = 0; m < 8; m++) {
            int c = tx + m * 32;
            float d2   = xs - 2.0f * acc[j][m] + msq[m];
            float dist = sqrtf(fmaxf(d2, 0.0f));
            float e    = expf(dist * sc);
            if (vld[m] && (c != cr)) part += e;
        }
        #pragma unroll
        for (int o = 16; o > 0; o >>= 1)
            part += __shfl_xor_sync(0xffffffffu, part, o);
        if (tx == 0 && g_valid[cr]) {
            lsum += logf(part) + 0.5f * g_rnorm[r] / stdev + ALPHA;
        }
    }
    if (tx == 0) atomicAdd(&g_stats[2], lsum);
}

// ---------------- K5: finalize ----------------
__global__ void k_final(float* __restrict__ out) {
    out[0] = g_stats[2] / g_stats[1];
}

// ---------------- launcher ----------------
extern "C" void kernel_launch(void* const* d_in, const int* in_sizes, int n_in,
                              void* d_out, int out_size) {
    const float* X  = (const float*)d_in[0];
    const int*   cl = (const int*)d_in[1];
    float* out = (float*)d_out;

    k_means<<<NC, 256>>>(X, cl);
    k_resid<<<N_INST, 256>>>(X, cl);
    k_stats<<<1, 256>>>(cl);
    k_gemm<<<N_INST / 32, 256>>>(X, cl);
    k_final<<<1, 1>>>(out);
}

// round 5
// speedup vs baseline: 2.6226x; 2.6226x over previous
#include <cuda_runtime.h>
#include <cuda_bf16.h>
#include <cstdint>
#include <math.h>

#define N_INST 8192
#define DIM    2048
#define NC     256
#define ALPHA  7.18f
#define MINM   4

// ---------------- scratch (no allocs allowed) ----------------
__device__ float g_means [NC * DIM];            // [C][D] fp32 (for resid pass)
__device__ __nv_bfloat16 g_meansB[NC * DIM];    // [C][D] bf16 (GEMM B operand)
__device__ __nv_bfloat16 g_Xbf  [N_INST * DIM]; // bf16 X (GEMM A operand)
__device__ float g_mean_sq[NC];
__device__ float g_counts [NC];
__device__ int   g_valid  [NC];
__device__ float g_xsq  [N_INST];
__device__ float g_rnorm[N_INST];
__device__ float g_stats[3];                    // [0]=stdev [1]=num_inst [2]=loss acc

// ---------------- K1: per-cluster means ----------------
__global__ void __launch_bounds__(256) k_means(const float* __restrict__ X,
                                               const int* __restrict__ cl) {
    __shared__ int   sh_list[N_INST];
    __shared__ int   sh_cnt[256];
    __shared__ int   sh_off[256];
    __shared__ float red[256];

    const int c = blockIdx.x;
    const int t = threadIdx.x;
    const int CH = N_INST / 256;

    int base = t * CH;
    int cnt = 0;
    #pragma unroll 8
    for (int j = 0; j < CH; j++) cnt += (cl[base + j] == c);
    sh_cnt[t] = cnt;
    __syncthreads();
    if (t == 0) {
        int s = 0;
        for (int i = 0; i < 256; i++) { sh_off[i] = s; s += sh_cnt[i]; }
    }
    __syncthreads();
    int off = sh_off[t];
    for (int j = 0; j < CH; j++) {
        int idx = base + j;
        if (cl[idx] == c) sh_list[off++] = idx;
    }
    __syncthreads();
    const int total = sh_off[255] + sh_cnt[255];

    float acc[8];
    #pragma unroll
    for (int j = 0; j < 8; j++) acc[j] = 0.0f;
    for (int m = 0; m < total; m++) {
        const float* row = X + (size_t)sh_list[m] * DIM;
        #pragma unroll
        for (int j = 0; j < 8; j++) acc[j] += row[t + j * 256];
    }

    const float inv = 1.0f / fmaxf((float)total, 1.0f);
    float msq = 0.0f;
    #pragma unroll
    for (int j = 0; j < 8; j++) {
        float mu = acc[j] * inv;
        int d = t + j * 256;
        g_means [(size_t)c * DIM + d] = mu;
        g_meansB[(size_t)c * DIM + d] = __float2bfloat16_rn(mu);
        msq += mu * mu;
    }
    red[t] = msq;
    __syncthreads();
    for (int s = 128; s > 0; s >>= 1) {
        if (t < s) red[t] += red[t + s];
        __syncthreads();
    }
    if (t == 0) {
        g_mean_sq[c] = red[0];
        g_counts[c]  = (float)total;
        g_valid[c]   = (total >= MINM) ? 1 : 0;
    }
}

// ---------------- K2: per-row ||x||^2, residual norm, bf16 convert ----------------
__global__ void __launch_bounds__(256) k_resid(const float* __restrict__ X,
                                               const int* __restrict__ cl) {
    __shared__ float r1[256], r2[256];
    const int i = blockIdx.x;
    const int t = threadIdx.x;
    const int c = cl[i];
    const float* row = X + (size_t)i * DIM;
    const float* mu  = g_means + (size_t)c * DIM;
    __nv_bfloat16* xb = g_Xbf + (size_t)i * DIM;

    float sx = 0.0f, sr = 0.0f;
    #pragma unroll
    for (int j = 0; j < 8; j++) {
        int d = t + j * 256;
        float x = row[d];
        float m = mu [d];
        xb[d] = __float2bfloat16_rn(x);
        sx += x * x;
        float dd = x - m;
        sr += dd * dd;
    }
    r1[t] = sx; r2[t] = sr;
    __syncthreads();
    for (int s = 128; s > 0; s >>= 1) {
        if (t < s) { r1[t] += r1[t + s]; r2[t] += r2[t + s]; }
        __syncthreads();
    }
    if (t == 0) {
        g_xsq  [i] = r1[0];
        g_rnorm[i] = sqrtf(r2[0]);
    }
}

// ---------------- K3: global stats ----------------
__global__ void __launch_bounds__(256) k_stats(const int* __restrict__ cl) {
    __shared__ float red[256];
    __shared__ float s_ni;
    const int t = threadIdx.x;

    red[t] = g_valid[t] ? g_counts[t] : 0.0f;
    __syncthreads();
    for (int s = 128; s > 0; s >>= 1) {
        if (t < s) red[t] += red[t + s];
        __syncthreads();
    }
    if (t == 0) s_ni = red[0];
    __syncthreads();

    float sn = 0.0f;
    for (int i = t; i < N_INST; i += 256)
        sn += g_valid[cl[i]] ? g_rnorm[i] : 0.0f;
    red[t] = sn;
    __syncthreads();
    for (int s = 128; s > 0; s >>= 1) {
        if (t < s) red[t] += red[t + s];
        __syncthreads();
    }
    if (t == 0) {
        float s = red[0];
        g_stats[0] = (s * s) / s_ni;
        g_stats[1] = s_ni;
        g_stats[2] = 0.0f;
    }
}

// ---------------- K4: bf16 HMMA GEMM + fused epilogue ----------------
// Block: 256 threads (8 warps, 2x4 M-by-N). Tile: BM=64, BN=256, BK=16.
// 3-stage cp.async pipeline. Smem pitch 24 bf16 (48B) -> conflict-free LDS.

#define BM 64
#define BN 256
#define BK 16
#define PITCH 24          // bf16 elements per smem row
#define KT (DIM / BK)     // 128 k-tiles
#define STAGES 3

__device__ __forceinline__ void cp_async16(uint32_t dst, const void* src) {
    asm volatile("cp.async.cg.shared.global [%0], [%1], 16;" :: "r"(dst), "l"(src));
}
__device__ __forceinline__ void cp_commit() {
    asm volatile("cp.async.commit_group;");
}
__device__ __forceinline__ void cp_wait2() {
    asm volatile("cp.async.wait_group 2;");
}
__device__ __forceinline__ void mma16816(float c[4], const uint32_t a[4],
                                         const uint32_t b[2]) {
    asm volatile(
        "mma.sync.aligned.m16n8k16.row.col.f32.bf16.bf16.f32 "
        "{%0,%1,%2,%3}, {%4,%5,%6,%7}, {%8,%9}, {%0,%1,%2,%3};"
        : "+f"(c[0]), "+f"(c[1]), "+f"(c[2]), "+f"(c[3])
        : "r"(a[0]), "r"(a[1]), "r"(a[2]), "r"(a[3]), "r"(b[0]), "r"(b[1]));
}

__global__ void __launch_bounds__(256) k_gemm(const int* __restrict__ cl) {
    __shared__ __nv_bfloat16 sA[STAGES][BM * PITCH];   // 3*1536*2  =  9216 B
    __shared__ __nv_bfloat16 sB[STAGES][BN * PITCH];   // 3*6144*2  = 36864 B
    __shared__ float sdenom[BM][4];                    //             1024 B
    __shared__ float sred[2];

    const int t    = threadIdx.x;
    const int wid  = t >> 5;
    const int l    = t & 31;
    const int wm   = wid >> 2;       // 0..1 : M
    const int wn   = wid & 3;        // 0..3 : N
    const int row0 = blockIdx.x * BM;

    float acc[2][8][4];
    #pragma unroll
    for (int mt = 0; mt < 2; mt++)
        #pragma unroll
        for (int nt = 0; nt < 8; nt++)
            #pragma unroll
            for (int i = 0; i < 4; i++) acc[mt][nt][i] = 0.0f;

    // load mappings
    const int a_row = t >> 1;              // 0..127 (only t<128 load A)
    const int a_ch  = (t & 1) * 8;
    const int b_row = t >> 1;              // + i*128
    const int b_ch  = (t & 1) * 8;

    const __nv_bfloat16* Asrc  = g_Xbf + (size_t)(row0 + a_row) * DIM + a_ch;
    const __nv_bfloat16* Bsrc0 = g_meansB + (size_t)b_row * DIM + b_ch;
    const __nv_bfloat16* Bsrc1 = g_meansB + (size_t)(b_row + 128) * DIM + b_ch;

    uint32_t sA_dst = (uint32_t)__cvta_generic_to_shared(
        &sA[0][a_row * PITCH + a_ch]);
    uint32_t sB_dst0 = (uint32_t)__cvta_generic_to_shared(
        &sB[0][b_row * PITCH + b_ch]);
    uint32_t sB_dst1 = (uint32_t)__cvta_generic_to_shared(
        &sB[0][(b_row + 128) * PITCH + b_ch]);
    const uint32_t stA = BM * PITCH * 2;   // bytes per A stage
    const uint32_t stB = BN * PITCH * 2;

    // prologue: stages 0,1
    #pragma unroll
    for (int s = 0; s < 2; s++) {
        int kk = s * BK;
        if (t < 128) cp_async16(sA_dst + s * stA, Asrc + kk);
        cp_async16(sB_dst0 + s * stB, Bsrc0 + kk);
        cp_async16(sB_dst1 + s * stB, Bsrc1 + kk);
        cp_commit();
    }

    const int ar = l >> 2;
    const int ak = (l & 3) * 2;

    int s_cur = 0;
    for (int kt = 0; kt < KT; kt++) {
        int s_nxt = (kt + 2) % STAGES;
        if (kt + 2 < KT) {
            int kk = (kt + 2) * BK;
            if (t < 128) cp_async16(sA_dst + s_nxt * stA, Asrc + kk);
            cp_async16(sB_dst0 + s_nxt * stB, Bsrc0 + kk);
            cp_async16(sB_dst1 + s_nxt * stB, Bsrc1 + kk);
        }
        cp_commit();
        cp_wait2();
        __syncthreads();

        const __nv_bfloat16* A_ = sA[s_cur];
        const __nv_bfloat16* B_ = sB[s_cur];

        uint32_t a[2][4];
        #pragma unroll
        for (int mt = 0; mt < 2; mt++) {
            int rb = wm * 32 + mt * 16;
            a[mt][0] = *(const uint32_t*)&A_[(rb + ar)     * PITCH + ak];
            a[mt][1] = *(const uint32_t*)&A_[(rb + ar + 8) * PITCH + ak];
            a[mt][2] = *(const uint32_t*)&A_[(rb + ar)     * PITCH + ak + 8];
            a[mt][3] = *(const uint32_t*)&A_[(rb + ar + 8) * PITCH + ak + 8];
        }
        #pragma unroll
        for (int nt = 0; nt < 8; nt++) {
            int bn = wn * 64 + nt * 8 + ar;
            uint32_t b[2];
            b[0] = *(const uint32_t*)&B_[bn * PITCH + ak];
            b[1] = *(const uint32_t*)&B_[bn * PITCH + ak + 8];
            mma16816(acc[0][nt], a[0], b);
            mma16816(acc[1][nt], a[1], b);
        }
        __syncthreads();
        s_cur = s_cur + 1 == STAGES ? 0 : s_cur + 1;
    }

    // ---------------- epilogue ----------------
    const float stdev = g_stats[0];
    const float sc = -0.5f / stdev;

    // per-thread rows: base + {0,8,16,24}; v = mt*2+half
    int rbase = row0 + wm * 32 + ar;
    float rxsq[4]; int rcl[4];
    #pragma unroll
    for (int v = 0; v < 4; v++) {
        int r = rbase + ((v & 1) * 8) + ((v >> 1) * 16);
        rxsq[v] = g_xsq[r];
        rcl[v]  = cl[r];
    }

    float p[4] = {0.f, 0.f, 0.f, 0.f};
    #pragma unroll
    for (int nt = 0; nt < 8; nt++) {
        int n0 = wn * 64 + nt * 8 + (l & 3) * 2;
        float msq0 = g_mean_sq[n0], msq1 = g_mean_sq[n0 + 1];
        int v0 = g_valid[n0], v1 = g_valid[n0 + 1];
        #pragma unroll
        for (int mt = 0; mt < 2; mt++) {
            #pragma unroll
            for (int half = 0; half < 2; half++) {
                int vi = mt * 2 + half;
                float d2a = rxsq[vi] - 2.0f * acc[mt][nt][half * 2]     + msq0;
                float d2b = rxsq[vi] - 2.0f * acc[mt][nt][half * 2 + 1] + msq1;
                float ea = expf(sc * sqrtf(fmaxf(d2a, 0.0f)));
                float eb = expf(sc * sqrtf(fmaxf(d2b, 0.0f)));
                if (v0 && n0     != rcl[vi]) p[vi] += ea;
                if (v1 && n0 + 1 != rcl[vi]) p[vi] += eb;
            }
        }
    }
    // quad reduce (lanes l, l^1, l^2 share the same rows)
    #pragma unroll
    for (int v = 0; v < 4; v++) {
        p[v] += __shfl_xor_sync(0xffffffffu, p[v], 1);
        p[v] += __shfl_xor_sync(0xffffffffu, p[v], 2);
    }
    if ((l & 3) == 0) {
        #pragma unroll
        for (int v = 0; v < 4; v++) {
            int lr = wm * 32 + ar + ((v & 1) * 8) + ((v >> 1) * 16);
            sdenom[lr][wn] = p[v];
        }
    }
    __syncthreads();

    if (t < BM) {
        int r = row0 + t;
        float denom = sdenom[t][0] + sdenom[t][1] + sdenom[t][2] + sdenom[t][3];
        int cr = cl[r];
        float term = 0.0f;
        if (g_valid[cr])
            term = logf(denom) + 0.5f * g_rnorm[r] / stdev + ALPHA;
        #pragma unroll
        for (int o = 16; o > 0; o >>= 1)
            term += __shfl_xor_sync(0xffffffffu, term, o);
        if ((t & 31) == 0) sred[t >> 5] = term;
    }
    __syncthreads();
    if (t == 0) atomicAdd(&g_stats[2], sred[0] + sred[1]);
}

// ---------------- K5: finalize ----------------
__global__ void k_final(float* __restrict__ out) {
    out[0] = g_stats[2] / g_stats[1];
}

// ---------------- launcher ----------------
extern "C" void kernel_launch(void* const* d_in, const int* in_sizes, int n_in,
                              void* d_out, int out_size) {
    const float* X  = (const float*)d_in[0];
    const int*   cl = (const int*)d_in[1];
    float* out = (float*)d_out;

    k_means<<<NC, 256>>>(X, cl);
    k_resid<<<N_INST, 256>>>(X, cl);
    k_stats<<<1, 256>>>(cl);
    k_gemm<<<N_INST / BM, 256>>>(cl);
    k_final<<<1, 1>>>(out);
}

// round 6
// speedup vs baseline: 2.7560x; 1.0508x over previous
#include <cuda_runtime.h>
#include <cuda_bf16.h>
#include <cstdint>
#include <math.h>

#define N_INST 8192
#define DIM    2048
#define NC     256
#define ALPHA  7.18f
#define MINM   4

// ---------------- scratch (no allocs allowed) ----------------
__device__ float g_means [NC * DIM];            // [C][D] fp32 (for resid pass)
__device__ __nv_bfloat16 g_meansB[NC * DIM];    // [C][D] bf16 (GEMM B operand)
__device__ __nv_bfloat16 g_Xbf  [N_INST * DIM]; // bf16 X (GEMM A operand)
__device__ float g_mean_sq[NC];
__device__ float g_counts [NC];
__device__ int   g_valid  [NC];
__device__ float g_xsq  [N_INST];
__device__ float g_rnorm[N_INST];
__device__ float g_stats[3];                    // [0]=stdev [1]=num_inst [2]=loss acc

// ---------------- K1: per-cluster means ----------------
__global__ void __launch_bounds__(256) k_means(const float* __restrict__ X,
                                               const int* __restrict__ cl) {
    __shared__ int   sh_list[N_INST];
    __shared__ int   sh_cnt[256];
    __shared__ int   sh_off[256];
    __shared__ float red[256];

    const int c = blockIdx.x;
    const int t = threadIdx.x;
    const int CH = N_INST / 256;

    int base = t * CH;
    int cnt = 0;
    #pragma unroll 8
    for (int j = 0; j < CH; j++) cnt += (cl[base + j] == c);
    sh_cnt[t] = cnt;
    __syncthreads();
    if (t == 0) {
        int s = 0;
        for (int i = 0; i < 256; i++) { sh_off[i] = s; s += sh_cnt[i]; }
    }
    __syncthreads();
    int off = sh_off[t];
    for (int j = 0; j < CH; j++) {
        int idx = base + j;
        if (cl[idx] == c) sh_list[off++] = idx;
    }
    __syncthreads();
    const int total = sh_off[255] + sh_cnt[255];

    // 2-way unrolled accumulation (double MLP)
    float acc[8], acc2[8];
    #pragma unroll
    for (int j = 0; j < 8; j++) { acc[j] = 0.0f; acc2[j] = 0.0f; }
    int m = 0;
    for (; m + 1 < total; m += 2) {
        const float* rowA = X + (size_t)sh_list[m]     * DIM;
        const float* rowB = X + (size_t)sh_list[m + 1] * DIM;
        #pragma unroll
        for (int j = 0; j < 8; j++) {
            acc [j] += rowA[t + j * 256];
            acc2[j] += rowB[t + j * 256];
        }
    }
    if (m < total) {
        const float* rowA = X + (size_t)sh_list[m] * DIM;
        #pragma unroll
        for (int j = 0; j < 8; j++) acc[j] += rowA[t + j * 256];
    }
    #pragma unroll
    for (int j = 0; j < 8; j++) acc[j] += acc2[j];

    const float inv = 1.0f / fmaxf((float)total, 1.0f);
    float msq = 0.0f;
    #pragma unroll
    for (int j = 0; j < 8; j++) {
        float mu = acc[j] * inv;
        int d = t + j * 256;
        g_means [(size_t)c * DIM + d] = mu;
        g_meansB[(size_t)c * DIM + d] = __float2bfloat16_rn(mu);
        msq += mu * mu;
    }
    red[t] = msq;
    __syncthreads();
    for (int s = 128; s > 0; s >>= 1) {
        if (t < s) red[t] += red[t + s];
        __syncthreads();
    }
    if (t == 0) {
        g_mean_sq[c] = red[0];
        g_counts[c]  = (float)total;
        g_valid[c]   = (total >= MINM) ? 1 : 0;
    }
}

// ---------------- K2: warp-per-row ||x||^2, residual norm, bf16 convert ----------------
__global__ void __launch_bounds__(256) k_resid(const float* __restrict__ X,
                                               const int* __restrict__ cl) {
    const int t = threadIdx.x;
    const int w = t >> 5;
    const int l = t & 31;
    const int i = blockIdx.x * 8 + w;          // row
    const int c = cl[i];
    const float4* row = (const float4*)(X + (size_t)i * DIM);
    const float4* mu  = (const float4*)(g_means + (size_t)c * DIM);
    uint2* xb = (uint2*)(g_Xbf + (size_t)i * DIM);

    float sx = 0.0f, sr = 0.0f;
    #pragma unroll
    for (int j = 0; j < 16; j++) {
        int d4 = l + j * 32;                   // float4 index
        float4 x = row[d4];
        float4 m = mu [d4];
        __nv_bfloat162 h0 = __floats2bfloat162_rn(x.x, x.y);
        __nv_bfloat162 h1 = __floats2bfloat162_rn(x.z, x.w);
        uint2 packed;
        packed.x = *(uint32_t*)&h0;
        packed.y = *(uint32_t*)&h1;
        xb[d4] = packed;
        sx += x.x * x.x + x.y * x.y + x.z * x.z + x.w * x.w;
        float a = x.x - m.x, b = x.y - m.y, cc = x.z - m.z, dd = x.w - m.w;
        sr += a * a + b * b + cc * cc + dd * dd;
    }
    #pragma unroll
    for (int o = 16; o > 0; o >>= 1) {
        sx += __shfl_xor_sync(0xffffffffu, sx, o);
        sr += __shfl_xor_sync(0xffffffffu, sr, o);
    }
    if (l == 0) {
        g_xsq  [i] = sx;
        g_rnorm[i] = sqrtf(sr);
    }
}

// ---------------- K3: global stats ----------------
__global__ void __launch_bounds__(256) k_stats(const int* __restrict__ cl) {
    __shared__ float red[256];
    __shared__ float s_ni;
    const int t = threadIdx.x;

    red[t] = g_valid[t] ? g_counts[t] : 0.0f;
    __syncthreads();
    for (int s = 128; s > 0; s >>= 1) {
        if (t < s) red[t] += red[t + s];
        __syncthreads();
    }
    if (t == 0) s_ni = red[0];
    __syncthreads();

    float sn = 0.0f;
    for (int i = t; i < N_INST; i += 256)
        sn += g_valid[cl[i]] ? g_rnorm[i] : 0.0f;
    red[t] = sn;
    __syncthreads();
    for (int s = 128; s > 0; s >>= 1) {
        if (t < s) red[t] += red[t + s];
        __syncthreads();
    }
    if (t == 0) {
        float s = red[0];
        g_stats[0] = (s * s) / s_ni;
        g_stats[1] = s_ni;
        g_stats[2] = 0.0f;
    }
}

// ---------------- K4: bf16 HMMA GEMM + fused epilogue ----------------
// Block: 256 threads (8 warps, 2x4 M-by-N). Tile: BM=64, BN=256, BK=16.
// 4-stage cp.async pipeline, prefetch distance 2, ONE __syncthreads per k-iter.

#define BM 64
#define BN 256
#define BK 16
#define PITCH 24          // bf16 elements per smem row
#define KT (DIM / BK)     // 128 k-tiles
#define STAGES 4

__device__ __forceinline__ void cp_async16(uint32_t dst, const void* src) {
    asm volatile("cp.async.cg.shared.global [%0], [%1], 16;" :: "r"(dst), "l"(src));
}
__device__ __forceinline__ void cp_commit() {
    asm volatile("cp.async.commit_group;");
}
__device__ __forceinline__ void cp_wait2() {
    asm volatile("cp.async.wait_group 2;");
}
__device__ __forceinline__ void mma16816(float c[4], const uint32_t a[4],
                                         const uint32_t b[2]) {
    asm volatile(
        "mma.sync.aligned.m16n8k16.row.col.f32.bf16.bf16.f32 "
        "{%0,%1,%2,%3}, {%4,%5,%6,%7}, {%8,%9}, {%0,%1,%2,%3};"
        : "+f"(c[0]), "+f"(c[1]), "+f"(c[2]), "+f"(c[3])
        : "r"(a[0]), "r"(a[1]), "r"(a[2]), "r"(a[3]), "r"(b[0]), "r"(b[1]));
}

__global__ void __launch_bounds__(256) k_gemm(const int* __restrict__ cl) {
    __shared__ __nv_bfloat16 sA[STAGES][BM * PITCH];   // 4*1536*2  = 12288 B
    __shared__ __nv_bfloat16 sB[STAGES][BN * PITCH];   // 4*6144*2  = 49152 B
    __shared__ float sdenom[BM][4];
    __shared__ float sred[2];

    const int t    = threadIdx.x;
    const int wid  = t >> 5;
    const int l    = t & 31;
    const int wm   = wid >> 2;       // 0..1 : M
    const int wn   = wid & 3;        // 0..3 : N
    const int row0 = blockIdx.x * BM;

    float acc[2][8][4];
    #pragma unroll
    for (int mt = 0; mt < 2; mt++)
        #pragma unroll
        for (int nt = 0; nt < 8; nt++)
            #pragma unroll
            for (int i = 0; i < 4; i++) acc[mt][nt][i] = 0.0f;

    // load mappings
    const int a_row = t >> 1;
    const int a_ch  = (t & 1) * 8;
    const int b_row = t >> 1;
    const int b_ch  = (t & 1) * 8;

    const __nv_bfloat16* Asrc  = g_Xbf + (size_t)(row0 + a_row) * DIM + a_ch;
    const __nv_bfloat16* Bsrc0 = g_meansB + (size_t)b_row * DIM + b_ch;
    const __nv_bfloat16* Bsrc1 = g_meansB + (size_t)(b_row + 128) * DIM + b_ch;

    uint32_t sA_dst = (uint32_t)__cvta_generic_to_shared(
        &sA[0][a_row * PITCH + a_ch]);
    uint32_t sB_dst0 = (uint32_t)__cvta_generic_to_shared(
        &sB[0][b_row * PITCH + b_ch]);
    uint32_t sB_dst1 = (uint32_t)__cvta_generic_to_shared(
        &sB[0][(b_row + 128) * PITCH + b_ch]);
    const uint32_t stA = BM * PITCH * 2;
    const uint32_t stB = BN * PITCH * 2;

    // prologue: stages 0,1
    #pragma unroll
    for (int s = 0; s < 2; s++) {
        int kk = s * BK;
        if (t < 128) cp_async16(sA_dst + s * stA, Asrc + kk);
        cp_async16(sB_dst0 + s * stB, Bsrc0 + kk);
        cp_async16(sB_dst1 + s * stB, Bsrc1 + kk);
        cp_commit();
    }

    const int ar = l >> 2;
    const int ak = (l & 3) * 2;

    int s_cur = 0;
    for (int kt = 0; kt < KT; kt++) {
        // issue prefetch for kt+2 into stage (kt+2)%4.
        // Safe: that stage was last READ at MMA(kt-2), which precedes the
        // barrier of iteration kt-1 that every warp has already passed.
        if (kt + 2 < KT) {
            int s_nxt = (kt + 2) & (STAGES - 1);
            int kk = (kt + 2) * BK;
            if (t < 128) cp_async16(sA_dst + s_nxt * stA, Asrc + kk);
            cp_async16(sB_dst0 + s_nxt * stB, Bsrc0 + kk);
            cp_async16(sB_dst1 + s_nxt * stB, Bsrc1 + kk);
        }
        cp_commit();
        cp_wait2();
        __syncthreads();

        const __nv_bfloat16* A_ = sA[s_cur];
        const __nv_bfloat16* B_ = sB[s_cur];

        uint32_t a[2][4];
        #pragma unroll
        for (int mt = 0; mt < 2; mt++) {
            int rb = wm * 32 + mt * 16;
            a[mt][0] = *(const uint32_t*)&A_[(rb + ar)     * PITCH + ak];
            a[mt][1] = *(const uint32_t*)&A_[(rb + ar + 8) * PITCH + ak];
            a[mt][2] = *(const uint32_t*)&A_[(rb + ar)     * PITCH + ak + 8];
            a[mt][3] = *(const uint32_t*)&A_[(rb + ar + 8) * PITCH + ak + 8];
        }
        #pragma unroll
        for (int nt = 0; nt < 8; nt++) {
            int bn = wn * 64 + nt * 8 + ar;
            uint32_t b[2];
            b[0] = *(const uint32_t*)&B_[bn * PITCH + ak];
            b[1] = *(const uint32_t*)&B_[bn * PITCH + ak + 8];
            mma16816(acc[0][nt], a[0], b);
            mma16816(acc[1][nt], a[1], b);
        }
        s_cur = (s_cur + 1) & (STAGES - 1);
    }

    // ---------------- epilogue ----------------
    const float stdev = g_stats[0];
    const float sc = -0.5f / stdev;

    int rbase = row0 + wm * 32 + ar;
    float rxsq[4]; int rcl[4];
    #pragma unroll
    for (int v = 0; v < 4; v++) {
        int r = rbase + ((v & 1) * 8) + ((v >> 1) * 16);
        rxsq[v] = g_xsq[r];
        rcl[v]  = cl[r];
    }

    float p[4] = {0.f, 0.f, 0.f, 0.f};
    #pragma unroll
    for (int nt = 0; nt < 8; nt++) {
        int n0 = wn * 64 + nt * 8 + (l & 3) * 2;
        float msq0 = g_mean_sq[n0], msq1 = g_mean_sq[n0 + 1];
        int v0 = g_valid[n0], v1 = g_valid[n0 + 1];
        #pragma unroll
        for (int mt = 0; mt < 2; mt++) {
            #pragma unroll
            for (int half = 0; half < 2; half++) {
                int vi = mt * 2 + half;
                float d2a = rxsq[vi] - 2.0f * acc[mt][nt][half * 2]     + msq0;
                float d2b = rxsq[vi] - 2.0f * acc[mt][nt][half * 2 + 1] + msq1;
                float ea = expf(sc * sqrtf(fmaxf(d2a, 0.0f)));
                float eb = expf(sc * sqrtf(fmaxf(d2b, 0.0f)));
                if (v0 && n0     != rcl[vi]) p[vi] += ea;
                if (v1 && n0 + 1 != rcl[vi]) p[vi] += eb;
            }
        }
    }
    #pragma unroll
    for (int v = 0; v < 4; v++) {
        p[v] += __shfl_xor_sync(0xffffffffu, p[v], 1);
        p[v] += __shfl_xor_sync(0xffffffffu, p[v], 2);
    }
    if ((l & 3) == 0) {
        #pragma unroll
        for (int v = 0; v < 4; v++) {
            int lr = wm * 32 + ar + ((v & 1) * 8) + ((v >> 1) * 16);
            sdenom[lr][wn] = p[v];
        }
    }
    __syncthreads();

    if (t < BM) {
        int r = row0 + t;
        float denom = sdenom[t][0] + sdenom[t][1] + sdenom[t][2] + sdenom[t][3];
        int cr = cl[r];
        float term = 0.0f;
        if (g_valid[cr])
            term = logf(denom) + 0.5f * g_rnorm[r] / stdev + ALPHA;
        #pragma unroll
        for (int o = 16; o > 0; o >>= 1)
            term += __shfl_xor_sync(0xffffffffu, term, o);
        if ((t & 31) == 0) sred[t >> 5] = term;
    }
    __syncthreads();
    if (t == 0) atomicAdd(&g_stats[2], sred[0] + sred[1]);
}

// ---------------- K5: finalize ----------------
__global__ void k_final(float* __restrict__ out) {
    out[0] = g_stats[2] / g_stats[1];
}

// ---------------- launcher ----------------
extern "C" void kernel_launch(void* const* d_in, const int* in_sizes, int n_in,
                              void* d_out, int out_size) {
    const float* X  = (const float*)d_in[0];
    const int*   cl = (const int*)d_in[1];
    float* out = (float*)d_out;

    k_means<<<NC, 256>>>(X, cl);
    k_resid<<<N_INST / 8, 256>>>(X, cl);
    k_stats<<<1, 256>>>(cl);
    k_gemm<<<N_INST / BM, 256>>>(cl);
    k_final<<<1, 1>>>(out);
}

// round 7
// speedup vs baseline: 3.3196x; 1.2045x over previous
#include <cuda_runtime.h>
#include <cuda_bf16.h>
#include <cstdint>
#include <math.h>

#define N_INST 8192
#define DIM    2048
#define NC     256
#define ALPHA  7.18f
#define MINM   4

// ---------------- scratch (no allocs allowed) ----------------
__device__ float g_means [NC * DIM];            // [C][D] fp32 (for resid pass)
__device__ __nv_bfloat16 g_meansB[NC * DIM];    // [C][D] bf16 (GEMM B operand)
__device__ __nv_bfloat16 g_Xbf  [N_INST * DIM]; // bf16 X (GEMM A operand)
__device__ float g_mean_sq[NC];
__device__ float g_counts [NC];
__device__ int   g_valid  [NC];
__device__ float g_xsq  [N_INST];
__device__ float g_rnorm[N_INST];
__device__ float g_stats[3];                    // [0]=stdev [1]=num_inst [2]=loss acc

__device__ __forceinline__ float fsqrt_approx(float x) {
    float y;
    asm("sqrt.approx.f32 %0, %1;" : "=f"(y) : "f"(x));
    return y;
}

// ---------------- K1: per-cluster means + bf16 conversion of X ----------------
__global__ void __launch_bounds__(256) k_means(const float* __restrict__ X,
                                               const int* __restrict__ cl) {
    __shared__ int   sh_list[N_INST];
    __shared__ int   sh_cnt[256];
    __shared__ int   sh_off[256];
    __shared__ float red[256];

    const int c = blockIdx.x;
    const int t = threadIdx.x;
    const int CH = N_INST / 256;

    int base = t * CH;
    int cnt = 0;
    #pragma unroll 8
    for (int j = 0; j < CH; j++) cnt += (cl[base + j] == c);
    sh_cnt[t] = cnt;
    __syncthreads();
    if (t == 0) {
        int s = 0;
        for (int i = 0; i < 256; i++) { sh_off[i] = s; s += sh_cnt[i]; }
    }
    __syncthreads();
    int off = sh_off[t];
    for (int j = 0; j < CH; j++) {
        int idx = base + j;
        if (cl[idx] == c) sh_list[off++] = idx;
    }
    __syncthreads();
    const int total = sh_off[255] + sh_cnt[255];

    // 2-way unrolled accumulation; also convert X rows to bf16 (each row is
    // touched by exactly one cluster block, so this covers all of X once).
    float acc[8], acc2[8];
    #pragma unroll
    for (int j = 0; j < 8; j++) { acc[j] = 0.0f; acc2[j] = 0.0f; }
    int m = 0;
    for (; m + 1 < total; m += 2) {
        int ra = sh_list[m], rb = sh_list[m + 1];
        const float* rowA = X + (size_t)ra * DIM;
        const float* rowB = X + (size_t)rb * DIM;
        __nv_bfloat16* xa = g_Xbf + (size_t)ra * DIM;
        __nv_bfloat16* xbb = g_Xbf + (size_t)rb * DIM;
        #pragma unroll
        for (int j = 0; j < 8; j++) {
            float va = rowA[t + j * 256];
            float vb = rowB[t + j * 256];
            acc [j] += va;
            acc2[j] += vb;
            xa [t + j * 256] = __float2bfloat16_rn(va);
            xbb[t + j * 256] = __float2bfloat16_rn(vb);
        }
    }
    if (m < total) {
        int ra = sh_list[m];
        const float* rowA = X + (size_t)ra * DIM;
        __nv_bfloat16* xa = g_Xbf + (size_t)ra * DIM;
        #pragma unroll
        for (int j = 0; j < 8; j++) {
            float va = rowA[t + j * 256];
            acc[j] += va;
            xa[t + j * 256] = __float2bfloat16_rn(va);
        }
    }
    #pragma unroll
    for (int j = 0; j < 8; j++) acc[j] += acc2[j];

    const float inv = 1.0f / fmaxf((float)total, 1.0f);
    float msq = 0.0f;
    #pragma unroll
    for (int j = 0; j < 8; j++) {
        float mu = acc[j] * inv;
        int d = t + j * 256;
        g_means [(size_t)c * DIM + d] = mu;
        g_meansB[(size_t)c * DIM + d] = __float2bfloat16_rn(mu);
        msq += mu * mu;
    }
    red[t] = msq;
    __syncthreads();
    for (int s = 128; s > 0; s >>= 1) {
        if (t < s) red[t] += red[t + s];
        __syncthreads();
    }
    if (t == 0) {
        g_mean_sq[c] = red[0];
        g_counts[c]  = (float)total;
        g_valid[c]   = (total >= MINM) ? 1 : 0;
    }
}

// ---------------- K2: warp-per-row xsq + residual norm from bf16 X ----------------
__global__ void __launch_bounds__(256) k_resid(const int* __restrict__ cl) {
    const int t = threadIdx.x;
    const int w = t >> 5;
    const int l = t & 31;
    const int i = blockIdx.x * 8 + w;
    const int c = cl[i];
    const uint4*  row = (const uint4*)(g_Xbf + (size_t)i * DIM);   // 8 bf16 per uint4
    const float4* mu  = (const float4*)(g_means + (size_t)c * DIM);

    float sx = 0.0f, sr = 0.0f;
    #pragma unroll
    for (int j = 0; j < 8; j++) {
        int d8 = l + j * 32;                   // uint4 index (8 bf16)
        uint4 v = row[d8];
        float4 m0 = mu[d8 * 2];
        float4 m1 = mu[d8 * 2 + 1];
        float2 x0 = __bfloat1622float2(*(const __nv_bfloat162*)&v.x);
        float2 x1 = __bfloat1622float2(*(const __nv_bfloat162*)&v.y);
        float2 x2 = __bfloat1622float2(*(const __nv_bfloat162*)&v.z);
        float2 x3 = __bfloat1622float2(*(const __nv_bfloat162*)&v.w);
        sx += x0.x*x0.x + x0.y*x0.y + x1.x*x1.x + x1.y*x1.y
            + x2.x*x2.x + x2.y*x2.y + x3.x*x3.x + x3.y*x3.y;
        float a0 = x0.x - m0.x, a1 = x0.y - m0.y, a2 = x1.x - m0.z, a3 = x1.y - m0.w;
        float a4 = x2.x - m1.x, a5 = x2.y - m1.y, a6 = x3.x - m1.z, a7 = x3.y - m1.w;
        sr += a0*a0 + a1*a1 + a2*a2 + a3*a3 + a4*a4 + a5*a5 + a6*a6 + a7*a7;
    }
    #pragma unroll
    for (int o = 16; o > 0; o >>= 1) {
        sx += __shfl_xor_sync(0xffffffffu, sx, o);
        sr += __shfl_xor_sync(0xffffffffu, sr, o);
    }
    if (l == 0) {
        g_xsq  [i] = sx;
        g_rnorm[i] = fsqrt_approx(sr);
    }
}

// ---------------- K3: global stats ----------------
__global__ void __launch_bounds__(256) k_stats(const int* __restrict__ cl) {
    __shared__ float red[256];
    __shared__ float s_ni;
    const int t = threadIdx.x;

    red[t] = g_valid[t] ? g_counts[t] : 0.0f;
    __syncthreads();
    for (int s = 128; s > 0; s >>= 1) {
        if (t < s) red[t] += red[t + s];
        __syncthreads();
    }
    if (t == 0) s_ni = red[0];
    __syncthreads();

    float sn = 0.0f;
    for (int i = t; i < N_INST; i += 256)
        sn += g_valid[cl[i]] ? g_rnorm[i] : 0.0f;
    red[t] = sn;
    __syncthreads();
    for (int s = 128; s > 0; s >>= 1) {
        if (t < s) red[t] += red[t + s];
        __syncthreads();
    }
    if (t == 0) {
        float s = red[0];
        g_stats[0] = (s * s) / s_ni;
        g_stats[1] = s_ni;
        g_stats[2] = 0.0f;
    }
}

// ---------------- K4: bf16 HMMA GEMM (ldmatrix) + Taylor-exp epilogue ----------------
#define BM 64
#define BN 256
#define BK 16
#define PITCH 24          // bf16 elements per smem row (48B, LDSM conflict-free)
#define KT (DIM / BK)
#define STAGES 4

__device__ __forceinline__ void cp_async16(uint32_t dst, const void* src) {
    asm volatile("cp.async.cg.shared.global [%0], [%1], 16;" :: "r"(dst), "l"(src));
}
__device__ __forceinline__ void cp_commit() {
    asm volatile("cp.async.commit_group;");
}
__device__ __forceinline__ void cp_wait2() {
    asm volatile("cp.async.wait_group 2;");
}
__device__ __forceinline__ void ldsm4(uint32_t& r0, uint32_t& r1, uint32_t& r2,
                                      uint32_t& r3, uint32_t addr) {
    asm volatile("ldmatrix.sync.aligned.m8n8.x4.shared.b16 {%0,%1,%2,%3}, [%4];"
                 : "=r"(r0), "=r"(r1), "=r"(r2), "=r"(r3) : "r"(addr));
}
__device__ __forceinline__ void mma16816(float c[4], const uint32_t a[4],
                                         const uint32_t b[2]) {
    asm volatile(
        "mma.sync.aligned.m16n8k16.row.col.f32.bf16.bf16.f32 "
        "{%0,%1,%2,%3}, {%4,%5,%6,%7}, {%8,%9}, {%0,%1,%2,%3};"
        : "+f"(c[0]), "+f"(c[1]), "+f"(c[2]), "+f"(c[3])
        : "r"(a[0]), "r"(a[1]), "r"(a[2]), "r"(a[3]), "r"(b[0]), "r"(b[1]));
}

__global__ void __launch_bounds__(256) k_gemm(const int* __restrict__ cl) {
    __shared__ __nv_bfloat16 sA[STAGES][BM * PITCH];
    __shared__ __nv_bfloat16 sB[STAGES][BN * PITCH];
    __shared__ float sdenom[BM][4];
    __shared__ float sred[2];

    const int t    = threadIdx.x;
    const int wid  = t >> 5;
    const int l    = t & 31;
    const int wm   = wid >> 2;       // 0..1 : M
    const int wn   = wid & 3;        // 0..3 : N
    const int row0 = blockIdx.x * BM;

    float acc[2][8][4];
    #pragma unroll
    for (int mt = 0; mt < 2; mt++)
        #pragma unroll
        for (int nt = 0; nt < 8; nt++)
            #pragma unroll
            for (int i = 0; i < 4; i++) acc[mt][nt][i] = 0.0f;

    // ---- cp.async load mappings ----
    const int a_row = t >> 1;
    const int a_ch  = (t & 1) * 8;

    const __nv_bfloat16* Asrc  = g_Xbf + (size_t)(row0 + a_row) * DIM + a_ch;
    const __nv_bfloat16* Bsrc0 = g_meansB + (size_t)a_row * DIM + a_ch;
    const __nv_bfloat16* Bsrc1 = g_meansB + (size_t)(a_row + 128) * DIM + a_ch;

    uint32_t sA_base = (uint32_t)__cvta_generic_to_shared(&sA[0][0]);
    uint32_t sB_base = (uint32_t)__cvta_generic_to_shared(&sB[0][0]);
    uint32_t sA_dst  = sA_base + (a_row * PITCH + a_ch) * 2;
    uint32_t sB_dst0 = sB_base + (a_row * PITCH + a_ch) * 2;
    uint32_t sB_dst1 = sB_base + ((a_row + 128) * PITCH + a_ch) * 2;
    const uint32_t stA = BM * PITCH * 2;
    const uint32_t stB = BN * PITCH * 2;

    // ---- ldmatrix per-lane smem offsets (bytes within a stage) ----
    // A x4: lanes 0-15 -> rows 0-15 (k 0-7); lanes 16-31 -> rows 0-15 (k 8-15)
    uint32_t aoff[2];
    #pragma unroll
    for (int mt = 0; mt < 2; mt++)
        aoff[mt] = ((wm * 32 + mt * 16 + (l & 15)) * PITCH + (l >> 4) * 8) * 2;
    // B x4 (pair p covers nt=2p,2p+1): mat = l>>3;
    //   n = wn*64 + p*16 + (l&7) + (mat>>1)*8 ; k = (mat&1)*8
    uint32_t boff[4];
    #pragma unroll
    for (int p = 0; p < 4; p++)
        boff[p] = ((wn * 64 + p * 16 + (l & 7) + ((l >> 4) & 1) * 8) * PITCH
                   + ((l >> 3) & 1) * 8) * 2;

    // prologue: stages 0,1
    #pragma unroll
    for (int s = 0; s < 2; s++) {
        int kk = s * BK;
        if (t < 128) cp_async16(sA_dst + s * stA, Asrc + kk);
        cp_async16(sB_dst0 + s * stB, Bsrc0 + kk);
        cp_async16(sB_dst1 + s * stB, Bsrc1 + kk);
        cp_commit();
    }

    int s_cur = 0;
    for (int kt = 0; kt < KT; kt++) {
        if (kt + 2 < KT) {
            int s_nxt = (kt + 2) & (STAGES - 1);
            int kk = (kt + 2) * BK;
            if (t < 128) cp_async16(sA_dst + s_nxt * stA, Asrc + kk);
            cp_async16(sB_dst0 + s_nxt * stB, Bsrc0 + kk);
            cp_async16(sB_dst1 + s_nxt * stB, Bsrc1 + kk);
        }
        cp_commit();
        cp_wait2();
        __syncthreads();

        uint32_t sa = sA_base + s_cur * stA;
        uint32_t sb = sB_base + s_cur * stB;

        uint32_t a[2][4];
        ldsm4(a[0][0], a[0][1], a[0][2], a[0][3], sa + aoff[0]);
        ldsm4(a[1][0], a[1][1], a[1][2], a[1][3], sa + aoff[1]);

        #pragma unroll
        for (int p = 0; p < 4; p++) {
            uint32_t b0[2], b1[2];
            ldsm4(b0[0], b0[1], b1[0], b1[1], sb + boff[p]);
            mma16816(acc[0][2 * p],     a[0], b0);
            mma16816(acc[1][2 * p],     a[1], b0);
            mma16816(acc[0][2 * p + 1], a[0], b1);
            mma16816(acc[1][2 * p + 1], a[1], b1);
        }
        s_cur = (s_cur + 1) & (STAGES - 1);
    }

    // ---------------- epilogue ----------------
    const float stdev = g_stats[0];
    const float sc = -0.5f / stdev;

    const int ar = l >> 2;
    const int ak2 = (l & 3) * 2;
    int rbase = row0 + wm * 32 + ar;
    float rxsq[4]; int rcl[4];
    #pragma unroll
    for (int v = 0; v < 4; v++) {
        int r = rbase + ((v & 1) * 8) + ((v >> 1) * 16);
        rxsq[v] = g_xsq[r];
        rcl[v]  = cl[r];
    }

    float p[4] = {0.f, 0.f, 0.f, 0.f};
    #pragma unroll
    for (int nt = 0; nt < 8; nt++) {
        int n0 = wn * 64 + nt * 8 + ak2;
        float msq0 = g_mean_sq[n0], msq1 = g_mean_sq[n0 + 1];
        int v0 = g_valid[n0], v1 = g_valid[n0 + 1];
        #pragma unroll
        for (int mt = 0; mt < 2; mt++) {
            #pragma unroll
            for (int half = 0; half < 2; half++) {
                int vi = mt * 2 + half;
                float d2a = rxsq[vi] - 2.0f * acc[mt][nt][half * 2]     + msq0;
                float d2b = rxsq[vi] - 2.0f * acc[mt][nt][half * 2 + 1] + msq1;
                float da = fsqrt_approx(fmaxf(d2a, 0.0f));
                float db = fsqrt_approx(fmaxf(d2b, 0.0f));
                // exp(sc*d) with |sc*d| ~ 1e-6: 2nd-order Taylor, exact to 1e-18
                float ta = sc * da, tb = sc * db;
                float ea = 1.0f + fmaf(0.5f * ta, ta, ta);
                float eb = 1.0f + fmaf(0.5f * tb, tb, tb);
                if (v0 && n0     != rcl[vi]) p[vi] += ea;
                if (v1 && n0 + 1 != rcl[vi]) p[vi] += eb;
            }
        }
    }
    #pragma unroll
    for (int v = 0; v < 4; v++) {
        p[v] += __shfl_xor_sync(0xffffffffu, p[v], 1);
        p[v] += __shfl_xor_sync(0xffffffffu, p[v], 2);
    }
    if ((l & 3) == 0) {
        #pragma unroll
        for (int v = 0; v < 4; v++) {
            int lr = wm * 32 + ar + ((v & 1) * 8) + ((v >> 1) * 16);
            sdenom[lr][wn] = p[v];
        }
    }
    __syncthreads();

    if (t < BM) {
        int r = row0 + t;
        float denom = sdenom[t][0] + sdenom[t][1] + sdenom[t][2] + sdenom[t][3];
        int cr = cl[r];
        float term = 0.0f;
        if (g_valid[cr])
            term = logf(denom) + 0.5f * g_rnorm[r] / stdev + ALPHA;
        #pragma unroll
        for (int o = 16; o > 0; o >>= 1)
            term += __shfl_xor_sync(0xffffffffu, term, o);
        if ((t & 31) == 0) sred[t >> 5] = term;
    }
    __syncthreads();
    if (t == 0) atomicAdd(&g_stats[2], sred[0] + sred[1]);
}

// ---------------- K5: finalize ----------------
__global__ void k_final(float* __restrict__ out) {
    out[0] = g_stats[2] / g_stats[1];
}

// ---------------- launcher ----------------
extern "C" void kernel_launch(void* const* d_in, const int* in_sizes, int n_in,
                              void* d_out, int out_size) {
    const float* X  = (const float*)d_in[0];
    const int*   cl = (const int*)d_in[1];
    float* out = (float*)d_out;

    k_means<<<NC, 256>>>(X, cl);
    k_resid<<<N_INST / 8, 256>>>(cl);
    k_stats<<<1, 256>>>(cl);
    k_gemm<<<N_INST / BM, 256>>>(cl);
    k_final<<<1, 1>>>(out);
}